// round 11
// baseline (speedup 1.0000x reference)
#include <cuda_runtime.h>

#define BB 4
#define CC 64
#define TN 64
#define NN 4096
#define GRID 256
#define XS 68            // smem row stride (floats): 16B-aligned, conflict-limited

typedef unsigned long long ull;

// scratch (allocation-free rule: __device__ globals, zero-initialized)
__device__ float g_upart[BB * 64 * CC];   // [b][tile][c]
__device__ float g_vpart[BB * 64 * CC];
__device__ unsigned g_bar;                // monotonic barrier counter

// ---- f32x2 packed helpers ---------------------------------------------------
__device__ __forceinline__ ull pack2(float lo, float hi) {
    ull r; asm("mov.b64 %0, {%1, %2};" : "=l"(r) : "f"(lo), "f"(hi)); return r;
}
__device__ __forceinline__ void unpack2(ull v, float& lo, float& hi) {
    asm("mov.b64 {%0, %1}, %2;" : "=f"(lo), "=f"(hi) : "l"(v));
}
__device__ __forceinline__ ull fma2(ull a, ull b, ull c) {
    ull d; asm("fma.rn.f32x2 %0, %1, %2, %3;" : "=l"(d) : "l"(a), "l"(b), "l"(c)); return d;
}

__device__ __forceinline__ float relutanh(float x) {
    if (x <= 0.f) return 0.f;
    float e = __expf(-2.f * x);
    return (1.f - e) * __frcp_rn(1.f + e);
}

// device-wide barrier: monotonic counter
__device__ __forceinline__ void grid_barrier(int tid) {
    __threadfence();
    __syncthreads();
    if (tid == 0) {
        unsigned old = atomicAdd(&g_bar, 1u);
        unsigned target = (old & ~(unsigned)(GRID - 1)) + GRID;
        unsigned vcur;
        do { vcur = *(volatile unsigned*)&g_bar; } while ((int)(vcur - target) < 0);
        __threadfence();
    }
    __syncthreads();
}

// -----------------------------------------------------------------------------
// Single fused kernel, ONE barrier. grid=256, 256 threads.
// blk -> (b = blk>>6, tile = blk&63), n0 = tile*64.
// Pre-barrier : stage x tile; transpose conv_w -> smem (per block, redundant);
//               full-row a for S (exact); tile-local a/d; BN fold local;
//               u/v TILE PARTIALS from smem tile -> g_upart/g_vpart.
// Post-barrier: aggregate u/v (64 L2 loads), p/q, split-acc f32x2 GEMM,
//               rank-1 + BN + ReLU epilogue (a/d from smem).
// -----------------------------------------------------------------------------
__global__ void __launch_bounds__(256, 2) k_fused(
        const float* __restrict__ x,
        const float* __restrict__ w,
        const float* __restrict__ conv_w,
        const float* __restrict__ conv_b,
        const float* __restrict__ gamma,
        const float* __restrict__ beta,
        const float* __restrict__ mean,
        const float* __restrict__ var,
        float* __restrict__ out) {
    extern __shared__ float sm[];
    float* xs  = sm;                  // [64][XS] x tile
    float* w0s = sm + CC * XS;        // [c][XS] (o in 0..63)
    float* w1s = w0s + CC * XS;
    __shared__ __align__(16) float a_s[64], d_s[64], ad_s[64];
    __shared__ __align__(16) float p_s[CC], q_s[CC], u_s[CC], v_s[CC];
    __shared__ __align__(16) float scale_s[CC], shift_s[CC];
    __shared__ float upart[4 * 64], vpart[4 * 64];
    __shared__ float red[8];
    __shared__ float S_sh;

    const int tid = threadIdx.x;
    const int blk = blockIdx.x;
    const int b = blk >> 6;
    const int tile = blk & 63;
    const int n0 = tile * TN;

    // ---- stage x tile [64][64] -> xs (stride XS) ----
    {
        const float* xb = x + (size_t)(b * CC) * NN + n0;
        #pragma unroll
        for (int k = 0; k < 4; k++) {
            int i = tid + k * 256;          // 1024 float4 = 64 rows x 16
            int cc2 = i >> 4, j = i & 15;
            float4 v4 = ((const float4*)(xb + cc2 * NN))[j];
            *(float4*)(xs + cc2 * XS + j * 4) = v4;
        }
    }

    // ---- full-row a for S (exact relutanh) ----
    {
        const float4* w4 = (const float4*)(w + b * NN);
        float s = 0.f;
        #pragma unroll
        for (int k = 0; k < 4; k++) {
            float4 wv = w4[tid + k * 256];
            s += relutanh(wv.x) + relutanh(wv.y) + relutanh(wv.z) + relutanh(wv.w);
        }
        #pragma unroll
        for (int off = 16; off; off >>= 1) s += __shfl_down_sync(0xffffffffu, s, off);
        if ((tid & 31) == 0) red[tid >> 5] = s;
    }

    // ---- transpose conv_w -> smem (overlaps S-reduction latency) ----
    // conv_w[o][k]: k<64 -> w0s[k][o], else w1s[k-64][o]
    for (int idx = tid; idx < CC * 2 * CC; idx += 256) {
        int o = idx >> 7;
        int kk = idx & 127;
        float val = conv_w[idx];
        if (kk < CC) w0s[kk * XS + o] = val;
        else         w1s[(kk - CC) * XS + o] = val;
    }

    // ---- BN fold (block-local) ----
    if (tid >= 128 && tid < 192) {
        int o = tid - 128;
        float sc = gamma[o] * rsqrtf(var[o] + 1e-5f);
        scale_s[o] = sc;
        shift_s[o] = fmaf(conv_b[o] - mean[o], sc, beta[o]);
    }
    __syncthreads();
    if (tid == 0) {
        float t = 0.f;
        #pragma unroll
        for (int i = 0; i < 8; i++) t += red[i];
        S_sh = t;
    }
    __syncthreads();

    // ---- tile-local a, d, a*d (only 64 values; exact) ----
    if (tid < 64) {
        float aa = relutanh(w[b * NN + n0 + tid]);
        float dd = rsqrtf(fmaf(aa, S_sh, 1.f));
        a_s[tid] = aa;
        d_s[tid] = dd;
        ad_s[tid] = aa * dd;
    }
    __syncthreads();

    // ---- u/v tile partials from smem tile ----
    {
        const int cpart = tid & 63;
        const int h = tid >> 6;                  // 0..3, 16 n each
        const float* xr = xs + cpart * XS + h * 16;
        const float* ap = a_s + h * 16;
        const float* dp = ad_s + h * 16;
        float su = 0.f, sv = 0.f;
        #pragma unroll
        for (int i = 0; i < 16; i += 2) {
            float2 xv = *(const float2*)(xr + i);
            su = fmaf(xv.x, ap[i], su);
            su = fmaf(xv.y, ap[i + 1], su);
            sv = fmaf(xv.x, dp[i], sv);
            sv = fmaf(xv.y, dp[i + 1], sv);
        }
        upart[h * 64 + cpart] = su;
        vpart[h * 64 + cpart] = sv;
    }
    __syncthreads();
    if (tid < 64) {
        g_upart[(b * 64 + tile) * CC + tid] =
            upart[tid] + upart[64 + tid] + upart[128 + tid] + upart[192 + tid];
    } else if (tid < 128) {
        int c = tid - 64;
        g_vpart[(b * 64 + tile) * CC + c] =
            vpart[c] + vpart[64 + c] + vpart[128 + c] + vpart[192 + c];
    }

    // ================= device-wide barrier =================
    grid_barrier(tid);

    // ---- aggregate u/v: 64 coalesced L2 loads each (fixed order) ----
    if (tid < 64) {
        float s = 0.f;
        #pragma unroll 8
        for (int t = 0; t < 64; t++) s += g_upart[(b * 64 + t) * CC + tid];
        u_s[tid] = s;
    } else if (tid < 128) {
        int c = tid - 64;
        float s = 0.f;
        #pragma unroll 8
        for (int t = 0; t < 64; t++) s += g_vpart[(b * 64 + t) * CC + c];
        v_s[c] = s;
    }
    __syncthreads();

    // ---- p[o] = sum_c W0t[c][o] u[c] ; q[o] = sum_c W1t[c][o] v[c] ----
    if (tid < 128) {
        const int o = tid & 63;
        const bool isq = tid >= 64;
        const float* W = isq ? w1s : w0s;
        const float* uv = isq ? v_s : u_s;
        float s = 0.f;
        #pragma unroll 8
        for (int cc2 = 0; cc2 < CC; cc2++) s = fmaf(W[cc2 * XS + o], uv[cc2], s);
        (isq ? q_s : p_s)[o] = s;
    }
    __syncthreads();

    // ---- GEMM (split accumulators, prefetch-by-1) ----
    const int warp = tid >> 5, lane = tid & 31;
    const int ow = warp << 3;           // 8 o per warp (4 o-pairs)
    const int nl = 2 * lane;            // 2 n per lane
    const int ng = n0 + nl;

    const float2 a2 = *(const float2*)(a_s + nl);
    const float2 d2 = *(const float2*)(d_s + nl);

    ull acc0[4][2], acc1[4][2];
    #pragma unroll
    for (int i = 0; i < 4; i++) {
        acc0[i][0] = acc0[i][1] = 0ull;
        acc1[i][0] = acc1[i][1] = 0ull;
    }

    const float* xp  = xs  + nl;
    const float* w0p = w0s + ow;
    const float* w1p = w1s + ow;

    float2 xv = *(const float2*)(xp);
    #pragma unroll 8
    for (int k = 0; k < CC; k++) {
        ull xd0 = pack2(xv.x, xv.x);
        ull xd1 = pack2(xv.y, xv.y);
        if (k + 1 < CC) xv = *(const float2*)(xp + (k + 1) * XS);
        ulonglong2 wa0 = *(const ulonglong2*)(w0p + k * XS);
        ulonglong2 wb0 = *(const ulonglong2*)(w0p + k * XS + 4);
        ulonglong2 wa1 = *(const ulonglong2*)(w1p + k * XS);
        ulonglong2 wb1 = *(const ulonglong2*)(w1p + k * XS + 4);
        acc0[0][0] = fma2(wa0.x, xd0, acc0[0][0]);
        acc0[0][1] = fma2(wa0.x, xd1, acc0[0][1]);
        acc0[1][0] = fma2(wa0.y, xd0, acc0[1][0]);
        acc0[1][1] = fma2(wa0.y, xd1, acc0[1][1]);
        acc0[2][0] = fma2(wb0.x, xd0, acc0[2][0]);
        acc0[2][1] = fma2(wb0.x, xd1, acc0[2][1]);
        acc0[3][0] = fma2(wb0.y, xd0, acc0[3][0]);
        acc0[3][1] = fma2(wb0.y, xd1, acc0[3][1]);
        acc1[0][0] = fma2(wa1.x, xd0, acc1[0][0]);
        acc1[0][1] = fma2(wa1.x, xd1, acc1[0][1]);
        acc1[1][0] = fma2(wa1.y, xd0, acc1[1][0]);
        acc1[1][1] = fma2(wa1.y, xd1, acc1[1][1]);
        acc1[2][0] = fma2(wb1.x, xd0, acc1[2][0]);
        acc1[2][1] = fma2(wb1.x, xd1, acc1[2][1]);
        acc1[3][0] = fma2(wb1.y, xd0, acc1[3][0]);
        acc1[3][1] = fma2(wb1.y, xd1, acc1[3][1]);
    }

    // ---- epilogue: y = acc0 + d^2*acc1 + p*a + q*(d*a) ; BN ; ReLU ----
    const ull ddp0 = pack2(d2.x * d2.x, d2.x * d2.x);
    const ull ddp1 = pack2(d2.y * d2.y, d2.y * d2.y);
    const ull ap0  = pack2(a2.x, a2.x);
    const ull ap1  = pack2(a2.y, a2.y);
    const ull dap0 = pack2(d2.x * a2.x, d2.x * a2.x);
    const ull dap1 = pack2(d2.y * a2.y, d2.y * a2.y);

    float* ob = out + (size_t)(b * CC) * NN + ng;
    #pragma unroll
    for (int j = 0; j < 4; j++) {
        const int o0 = ow + 2 * j;
        ull pp = *(const ull*)(p_s + o0);
        ull qq = *(const ull*)(q_s + o0);
        ull sc = *(const ull*)(scale_s + o0);
        ull sh = *(const ull*)(shift_s + o0);
        ull y0 = fma2(acc1[j][0], ddp0, acc0[j][0]);
        y0 = fma2(pp, ap0, y0);
        y0 = fma2(qq, dap0, y0);
        y0 = fma2(y0, sc, sh);
        ull y1 = fma2(acc1[j][1], ddp1, acc0[j][1]);
        y1 = fma2(pp, ap1, y1);
        y1 = fma2(qq, dap1, y1);
        y1 = fma2(y1, sc, sh);
        float f00, f10, f01, f11;
        unpack2(y0, f00, f10);
        unpack2(y1, f01, f11);
        f00 = fmaxf(f00, 0.f); f01 = fmaxf(f01, 0.f);
        f10 = fmaxf(f10, 0.f); f11 = fmaxf(f11, 0.f);
        *(float2*)(ob + (size_t)o0 * NN)       = make_float2(f00, f01);
        *(float2*)(ob + (size_t)(o0 + 1) * NN) = make_float2(f10, f11);
    }
}

// -----------------------------------------------------------------------------
extern "C" void kernel_launch(void* const* d_in, const int* in_sizes, int n_in,
                              void* d_out, int out_size) {
    const float* x      = (const float*)d_in[0];
    const float* w      = (const float*)d_in[1];
    const float* conv_w = (const float*)d_in[2];
    const float* conv_b = (const float*)d_in[3];
    const float* gamma  = (const float*)d_in[4];
    const float* beta   = (const float*)d_in[5];
    const float* mean   = (const float*)d_in[6];
    const float* var    = (const float*)d_in[7];
    float* out = (float*)d_out;

    const int smem = 3 * CC * XS * sizeof(float);   // ~51 KB
    cudaFuncSetAttribute(k_fused, cudaFuncAttributeMaxDynamicSharedMemorySize, smem);

    k_fused<<<GRID, 256, smem>>>(x, w, conv_w, conv_b, gamma, beta, mean, var, out);
}

// round 12
// speedup vs baseline: 1.0437x; 1.0437x over previous
#include <cuda_runtime.h>

#define BB 4
#define CC 64
#define TN 64
#define NN 4096
#define GRID 512

typedef unsigned long long ull;

// scratch (allocation-free rule: __device__ globals, zero-initialized)
__device__ float g_a[BB * NN];
__device__ float g_d[BB * NN];
__device__ float g_u[BB * CC];
__device__ float g_v[BB * CC];
__device__ float g_W0t[CC * CC];     // [c][o]
__device__ float g_W1t[CC * CC];     // [c][o]
__device__ unsigned g_bar;           // monotonic barrier counter

// ---- f32x2 packed helpers ---------------------------------------------------
__device__ __forceinline__ ull pack2(float lo, float hi) {
    ull r; asm("mov.b64 %0, {%1, %2};" : "=l"(r) : "f"(lo), "f"(hi)); return r;
}
__device__ __forceinline__ void unpack2(ull v, float& lo, float& hi) {
    asm("mov.b64 {%0, %1}, %2;" : "=f"(lo), "=f"(hi) : "l"(v));
}
__device__ __forceinline__ ull fma2(ull a, ull b, ull c) {
    ull d; asm("fma.rn.f32x2 %0, %1, %2, %3;" : "=l"(d) : "l"(a), "l"(b), "l"(c)); return d;
}

__device__ __forceinline__ float relutanh(float x) {
    if (x <= 0.f) return 0.f;
    float e = __expf(-2.f * x);
    return (1.f - e) * __frcp_rn(1.f + e);
}

// device-wide barrier: monotonic counter (GRID power of 2)
__device__ __forceinline__ void grid_barrier(int tid) {
    __threadfence();
    __syncthreads();
    if (tid == 0) {
        unsigned old = atomicAdd(&g_bar, 1u);
        unsigned target = (old & ~(unsigned)(GRID - 1)) + GRID;
        unsigned vcur;
        do { vcur = *(volatile unsigned*)&g_bar; } while ((int)(vcur - target) < 0);
        __threadfence();
    }
    __syncthreads();
}

// -----------------------------------------------------------------------------
// grid=512, 256 threads, 32KB dyn smem, 4 blocks/SM (64-reg cap).
// blk -> b = blk>>7, tile = (blk&127)>>1, half = blk&1. n0 = tile*64.
// Block computes o in [half*32, half*32+32) x n in [n0, n0+64).
// Pre-barrier : stage x tile (all); half==0: full phase 1 (a,S,d,u,v for
//               c=tile, g_a/g_d writes if tile==0); half==1 && b==0:
//               transpose conv_w row c=tile; all: local BN fold.
// Post-barrier: stage weight half, u/v from global, p/q (32 o),
//               split-acc f32x2 GEMM (4 o/warp), epilogue.
// -----------------------------------------------------------------------------
__global__ void __launch_bounds__(256, 4) k_fused(
        const float* __restrict__ x,
        const float* __restrict__ w,
        const float* __restrict__ conv_w,
        const float* __restrict__ conv_b,
        const float* __restrict__ gamma,
        const float* __restrict__ beta,
        const float* __restrict__ mean,
        const float* __restrict__ var,
        float* __restrict__ out) {
    extern __shared__ float sm[];
    float* xs  = sm;                  // [64][64] x tile   16KB
    float* w0s = sm + CC * TN;        // [64 c][32 o]       8KB
    float* w1s = w0s + CC * 32;       //                    8KB
    __shared__ __align__(16) float p_s[32], q_s[32], scale_s[32], shift_s[32];
    __shared__ __align__(16) float u_s[CC], v_s[CC];
    __shared__ float red[8], red2[8];
    __shared__ float S_sh;

    const int tid = threadIdx.x;
    const int blk = blockIdx.x;
    const int b = blk >> 7;
    const int tile = (blk & 127) >> 1;
    const int half = blk & 1;
    const int n0 = tile * TN;
    const int ohalf = half * 32;

    // ---- stage x tile [64][64] (all blocks; needed post-barrier) ----
    {
        const float* xb = x + (size_t)(b * CC) * NN + n0;
        float4* xs4 = (float4*)xs;
        #pragma unroll
        for (int k = 0; k < 4; k++) {
            int i = tid + k * 256;          // 1024 float4 = 64 rows x 16
            int cc2 = i >> 4, j = i & 15;
            xs4[i] = ((const float4*)(xb + cc2 * NN))[j];
        }
    }

    // ---- local BN fold for this o-half ----
    if (tid >= 128 && tid < 160) {
        int j = tid - 128;
        int o = ohalf + j;
        float sc = gamma[o] * rsqrtf(var[o] + 1e-5f);
        scale_s[j] = sc;
        shift_s[j] = fmaf(conv_b[o] - mean[o], sc, beta[o]);
    }

    if (half == 0) {
        // ---- full phase 1 for channel c = tile (R10-identical) ----
        const int c = tile;
        const float4* w4 = (const float4*)(w + b * NN);
        float avr[16], dvr[16];
        float s = 0.f;
        #pragma unroll
        for (int k = 0; k < 4; k++) {
            float4 wv = w4[tid + k * 256];
            avr[k*4+0] = relutanh(wv.x);
            avr[k*4+1] = relutanh(wv.y);
            avr[k*4+2] = relutanh(wv.z);
            avr[k*4+3] = relutanh(wv.w);
            s += avr[k*4+0] + avr[k*4+1] + avr[k*4+2] + avr[k*4+3];
        }
        #pragma unroll
        for (int off = 16; off; off >>= 1) s += __shfl_down_sync(0xffffffffu, s, off);
        if ((tid & 31) == 0) red[tid >> 5] = s;
        __syncthreads();
        if (tid == 0) {
            float t = 0.f;
            #pragma unroll
            for (int i = 0; i < 8; i++) t += red[i];
            S_sh = t;
        }
        __syncthreads();
        const float S = S_sh;
        #pragma unroll
        for (int i = 0; i < 16; i++) dvr[i] = rsqrtf(fmaf(avr[i], S, 1.f));

        if (c == 0) {
            #pragma unroll
            for (int k = 0; k < 4; k++) {
                ((float4*)(g_a + b * NN))[tid + k * 256] =
                    make_float4(avr[k*4+0], avr[k*4+1], avr[k*4+2], avr[k*4+3]);
                ((float4*)(g_d + b * NN))[tid + k * 256] =
                    make_float4(dvr[k*4+0], dvr[k*4+1], dvr[k*4+2], dvr[k*4+3]);
            }
        }

        // u = sum x*a ; v = sum x*a*d for channel (b,c)
        const float4* x4 = (const float4*)(x + (size_t)(b * CC + c) * NN);
        float su = 0.f, sv = 0.f;
        #pragma unroll
        for (int k = 0; k < 4; k++) {
            float4 xv = x4[tid + k * 256];
            float t0 = xv.x * avr[k*4+0], t1 = xv.y * avr[k*4+1];
            float t2 = xv.z * avr[k*4+2], t3 = xv.w * avr[k*4+3];
            su += t0 + t1 + t2 + t3;
            sv += t0 * dvr[k*4+0] + t1 * dvr[k*4+1] + t2 * dvr[k*4+2] + t3 * dvr[k*4+3];
        }
        #pragma unroll
        for (int off = 16; off; off >>= 1) {
            su += __shfl_down_sync(0xffffffffu, su, off);
            sv += __shfl_down_sync(0xffffffffu, sv, off);
        }
        if ((tid & 31) == 0) { red[tid >> 5] = su; red2[tid >> 5] = sv; }
        __syncthreads();
        if (tid == 0) {
            float tu = 0.f, tv = 0.f;
            #pragma unroll
            for (int i = 0; i < 8; i++) { tu += red[i]; tv += red2[i]; }
            g_u[b * CC + c] = tu;
            g_v[b * CC + c] = tv;
        }
    } else if (b == 0) {
        // ---- transpose conv_w row c = tile into global c-major ----
        if (tid < CC) {
            g_W0t[tile * CC + tid] = conv_w[tid * 128 + tile];
            g_W1t[tile * CC + tid] = conv_w[tid * 128 + CC + tile];
        }
    }

    // ================= device-wide barrier =================
    grid_barrier(tid);

    // ---- stage this block's weight half: [64 c][32 o] ----
    {
        float4* w0s4 = (float4*)w0s;
        float4* w1s4 = (float4*)w1s;
        #pragma unroll
        for (int k = 0; k < 2; k++) {
            int i = tid + k * 256;          // 512 float4 = 64 rows x 8
            int cc2 = i >> 3, j4 = i & 7;
            w0s4[i] = *(const float4*)(g_W0t + cc2 * CC + ohalf + j4 * 4);
            w1s4[i] = *(const float4*)(g_W1t + cc2 * CC + ohalf + j4 * 4);
        }
        if (tid < CC) {
            u_s[tid] = g_u[b * CC + tid];
        } else if (tid < 128) {
            v_s[tid - 64] = g_v[b * CC + tid - 64];
        }
    }
    __syncthreads();

    // ---- p/q for this half's 32 o ----
    if (tid < 64) {
        const int j = tid & 31;
        const bool isq = tid >= 32;
        const float* W = isq ? w1s : w0s;
        const float* uv = isq ? v_s : u_s;
        float s = 0.f;
        #pragma unroll 8
        for (int cc2 = 0; cc2 < CC; cc2++) s = fmaf(W[cc2 * 32 + j], uv[cc2], s);
        (isq ? q_s : p_s)[j] = s;
    }
    __syncthreads();

    // ---- GEMM: warp owns 4 o (2 o-pairs), lane owns 2 n ----
    const int warp = tid >> 5, lane = tid & 31;
    const int ow = warp << 2;           // local o base (0..28)
    const int nl = 2 * lane;
    const int ng = n0 + nl;

    const float2 a2 = *(const float2*)(g_a + b * NN + ng);   // plain loads
    const float2 d2 = *(const float2*)(g_d + b * NN + ng);

    ull acc0[2][2], acc1[2][2];
    #pragma unroll
    for (int i = 0; i < 2; i++) {
        acc0[i][0] = acc0[i][1] = 0ull;
        acc1[i][0] = acc1[i][1] = 0ull;
    }

    const float* xp  = xs  + nl;
    const float* w0p = w0s + ow;
    const float* w1p = w1s + ow;

    float2 xv = *(const float2*)(xp);
    #pragma unroll 8
    for (int k = 0; k < CC; k++) {
        ull xd0 = pack2(xv.x, xv.x);
        ull xd1 = pack2(xv.y, xv.y);
        xv = *(const float2*)(xp + ((k + 1) & 63) * TN);   // always in-bounds
        ulonglong2 wa0 = *(const ulonglong2*)(w0p + k * 32);   // 4 o of W0
        ulonglong2 wa1 = *(const ulonglong2*)(w1p + k * 32);   // 4 o of W1
        acc0[0][0] = fma2(wa0.x, xd0, acc0[0][0]);
        acc0[0][1] = fma2(wa0.x, xd1, acc0[0][1]);
        acc0[1][0] = fma2(wa0.y, xd0, acc0[1][0]);
        acc0[1][1] = fma2(wa0.y, xd1, acc0[1][1]);
        acc1[0][0] = fma2(wa1.x, xd0, acc1[0][0]);
        acc1[0][1] = fma2(wa1.x, xd1, acc1[0][1]);
        acc1[1][0] = fma2(wa1.y, xd0, acc1[1][0]);
        acc1[1][1] = fma2(wa1.y, xd1, acc1[1][1]);
    }

    // ---- epilogue: y = acc0 + d^2*acc1 + p*a + q*(d*a) ; BN ; ReLU ----
    const ull ddp0 = pack2(d2.x * d2.x, d2.x * d2.x);
    const ull ddp1 = pack2(d2.y * d2.y, d2.y * d2.y);
    const ull ap0  = pack2(a2.x, a2.x);
    const ull ap1  = pack2(a2.y, a2.y);
    const ull dap0 = pack2(d2.x * a2.x, d2.x * a2.x);
    const ull dap1 = pack2(d2.y * a2.y, d2.y * a2.y);

    float* ob = out + (size_t)(b * CC + ohalf) * NN + ng;
    #pragma unroll
    for (int j = 0; j < 2; j++) {
        const int ol = ow + 2 * j;              // local o-pair index
        ull pp = *(const ull*)(p_s + ol);
        ull qq = *(const ull*)(q_s + ol);
        ull sc = *(const ull*)(scale_s + ol);
        ull sh = *(const ull*)(shift_s + ol);
        ull y0 = fma2(acc1[j][0], ddp0, acc0[j][0]);
        y0 = fma2(pp, ap0, y0);
        y0 = fma2(qq, dap0, y0);
        y0 = fma2(y0, sc, sh);
        ull y1 = fma2(acc1[j][1], ddp1, acc0[j][1]);
        y1 = fma2(pp, ap1, y1);
        y1 = fma2(qq, dap1, y1);
        y1 = fma2(y1, sc, sh);
        float f00, f10, f01, f11;
        unpack2(y0, f00, f10);     // (o, n0), (o+1, n0)
        unpack2(y1, f01, f11);     // (o, n1), (o+1, n1)
        f00 = fmaxf(f00, 0.f); f01 = fmaxf(f01, 0.f);
        f10 = fmaxf(f10, 0.f); f11 = fmaxf(f11, 0.f);
        *(float2*)(ob + (size_t)ol * NN)       = make_float2(f00, f01);
        *(float2*)(ob + (size_t)(ol + 1) * NN) = make_float2(f10, f11);
    }
}

// -----------------------------------------------------------------------------
extern "C" void kernel_launch(void* const* d_in, const int* in_sizes, int n_in,
                              void* d_out, int out_size) {
    const float* x      = (const float*)d_in[0];
    const float* w      = (const float*)d_in[1];
    const float* conv_w = (const float*)d_in[2];
    const float* conv_b = (const float*)d_in[3];
    const float* gamma  = (const float*)d_in[4];
    const float* beta   = (const float*)d_in[5];
    const float* mean   = (const float*)d_in[6];
    const float* var    = (const float*)d_in[7];
    float* out = (float*)d_out;

    const int smem = (CC * TN + 2 * CC * 32) * sizeof(float);  // 32 KB
    cudaFuncSetAttribute(k_fused, cudaFuncAttributeMaxDynamicSharedMemorySize, smem);

    k_fused<<<GRID, 256, smem>>>(x, w, conv_w, conv_b, gamma, beta, mean, var, out);
}

// round 14
// speedup vs baseline: 1.1515x; 1.1033x over previous
#include <cuda_runtime.h>
#include <cuda_bf16.h>
#include <cstdint>

#define BB 4
#define CC 64
#define NT 64
#define NN 4096
#define GRID 256

typedef unsigned long long ull;

// ---- scratch ----------------------------------------------------------------
__device__ float g_u[BB * CC];
__device__ float g_v[BB * CC];
__device__ unsigned g_bar;

// ---- dynamic smem map (bytes) ----------------------------------------------
#define SM_AHI   0        // [128 m][64 k] bf16 SW128  16384
#define SM_ALO   16384
#define SM_BHI   32768    // [64 n][64 k] bf16 SW128    8192
#define SM_BLO   40960
#define SM_META  49152    // float4[64] {a, a*d, d*d}
#define SM_PS    50176
#define SM_QS    50432
#define SM_SC    50688
#define SM_SH    50944
#define SM_US    51200
#define SM_VS    51456
#define SM_PPART 51712    // 256 f
#define SM_QPART 52736    // 256 f
#define SM_RED   53760
#define SM_RED2  53792
#define SM_SSUM  53824
#define SM_TOTAL 53888
#define SM_DS1   0        // post-barrier overlay (A/B dead): 64 o x 72 stride

#define SWZ(o) ((o) ^ (((o) >> 3) & 0x70))

static __device__ __forceinline__ uint32_t smem_u32(const void* p) {
    uint32_t a;
    asm("{ .reg .u64 t; cvta.to.shared.u64 t, %1; cvt.u32.u64 %0, t; }" : "=r"(a) : "l"(p));
    return a;
}
static __device__ __forceinline__ void ldsm4(uint32_t* r, uint32_t addr) {
    asm volatile("ldmatrix.sync.aligned.m8n8.x4.shared.b16 {%0,%1,%2,%3}, [%4];"
        : "=r"(r[0]), "=r"(r[1]), "=r"(r[2]), "=r"(r[3]) : "r"(addr));
}
static __device__ __forceinline__ void mma_bf16(float* d, const uint32_t* a,
                                                uint32_t b0, uint32_t b1) {
    asm volatile("mma.sync.aligned.m16n8k16.row.col.f32.bf16.bf16.f32 "
        "{%0,%1,%2,%3}, {%4,%5,%6,%7}, {%8,%9}, {%0,%1,%2,%3};"
        : "+f"(d[0]), "+f"(d[1]), "+f"(d[2]), "+f"(d[3])
        : "r"(a[0]), "r"(a[1]), "r"(a[2]), "r"(a[3]), "r"(b0), "r"(b1));
}

static __device__ __forceinline__ float relutanh(float x) {
    if (x <= 0.f) return 0.f;
    float e = __expf(-2.f * x);
    return (1.f - e) * __frcp_rn(1.f + e);
}

static __device__ __forceinline__ void grid_barrier(int tid) {
    __threadfence();
    __syncthreads();
    if (tid == 0) {
        unsigned old = atomicAdd(&g_bar, 1u);
        unsigned target = (old & ~(unsigned)(GRID - 1)) + GRID;
        unsigned vcur;
        do { vcur = *(volatile unsigned*)&g_bar; } while ((int)(vcur - target) < 0);
        __threadfence();
    }
    __syncthreads();
}

static __device__ __forceinline__ void split_store(char* bhi, char* blo,
                                                   uint32_t off, float val) {
    __nv_bfloat16 hi = __float2bfloat16(val);
    __nv_bfloat16 lo = __float2bfloat16(val - __bfloat162float(hi));
    uint32_t sw = SWZ(off);
    *(__nv_bfloat16*)(bhi + sw) = hi;
    *(__nv_bfloat16*)(blo + sw) = lo;
}

// -----------------------------------------------------------------------------
// grid=256, 256 threads. blk -> (b = blk>>6, tile = blk&63), n0 = tile*64.
// Pre-barrier : stage A=[W0;W1] hi/lo + B=x^T hi/lo (SW128); BN fold; phase 1
//               (a,S,d,u,v for c=tile -> g_u/g_v; tile meta); warp MMA into
//               registers (96 HMMA/warp, 3-term bf16).
// Post-barrier: u/v -> p/q; warps 4-7 bounce D1 via smem; warps 0-3 combine
//               y = D0 + d^2 D1 + p a + q (a d), BN, ReLU, store.
// -----------------------------------------------------------------------------
__global__ void __launch_bounds__(256, 2) k_fused(
        const float* __restrict__ x,
        const float* __restrict__ w,
        const float* __restrict__ conv_w,
        const float* __restrict__ conv_b,
        const float* __restrict__ gamma,
        const float* __restrict__ beta,
        const float* __restrict__ mean,
        const float* __restrict__ var,
        float* __restrict__ out) {
    extern __shared__ char smem[];
    const uint32_t smb = smem_u32(smem);

    float4* meta = (float4*)(smem + SM_META);
    float* p_s   = (float*)(smem + SM_PS);
    float* q_s   = (float*)(smem + SM_QS);
    float* sc_s  = (float*)(smem + SM_SC);
    float* sh_s  = (float*)(smem + SM_SH);
    float* u_s   = (float*)(smem + SM_US);
    float* v_s   = (float*)(smem + SM_VS);
    float* ppart = (float*)(smem + SM_PPART);
    float* qpart = (float*)(smem + SM_QPART);
    float* red   = (float*)(smem + SM_RED);
    float* red2  = (float*)(smem + SM_RED2);

    const int tid = threadIdx.x;
    const int wid = tid >> 5, lid = tid & 31;
    const int blk = blockIdx.x;
    const int b = blk >> 6;
    const int tile = blk & 63;
    const int n0 = tile * NT;

    // ---- stage A = [W0;W1] hi/lo, SW128, [m][k=c] ----
    {
        #pragma unroll
        for (int k = 0; k < 8; k++) {
            int i4 = tid + k * 256;              // 2048 float4
            int m = i4 >> 4, cb = (i4 & 15) * 4;
            const float* src = (m < CC) ? (conv_w + m * 128 + cb)
                                        : (conv_w + (m - CC) * 128 + CC + cb);
            float4 wv = *(const float4*)src;
            split_store(smem + SM_AHI, smem + SM_ALO, (uint32_t)(m * 128 + (cb + 0) * 2), wv.x);
            split_store(smem + SM_AHI, smem + SM_ALO, (uint32_t)(m * 128 + (cb + 1) * 2), wv.y);
            split_store(smem + SM_AHI, smem + SM_ALO, (uint32_t)(m * 128 + (cb + 2) * 2), wv.z);
            split_store(smem + SM_AHI, smem + SM_ALO, (uint32_t)(m * 128 + (cb + 3) * 2), wv.w);
        }
    }
    // ---- stage B[n][c] = x[c][n0+n] hi/lo, SW128 ----
    {
        const int c = tid >> 2;                 // 0..63
        const int nc = (tid & 3) * 16;
        const float* xr = x + (size_t)(b * CC + c) * NN + n0 + nc;
        #pragma unroll
        for (int q4 = 0; q4 < 4; q4++) {
            float4 xv = *(const float4*)(xr + q4 * 4);
            int n = nc + q4 * 4;
            split_store(smem + SM_BHI, smem + SM_BLO, (uint32_t)((n + 0) * 128 + c * 2), xv.x);
            split_store(smem + SM_BHI, smem + SM_BLO, (uint32_t)((n + 1) * 128 + c * 2), xv.y);
            split_store(smem + SM_BHI, smem + SM_BLO, (uint32_t)((n + 2) * 128 + c * 2), xv.z);
            split_store(smem + SM_BHI, smem + SM_BLO, (uint32_t)((n + 3) * 128 + c * 2), xv.w);
        }
    }
    // ---- BN fold ----
    if (tid >= 128 && tid < 192) {
        int o = tid - 128;
        float sc = gamma[o] * rsqrtf(var[o] + 1e-5f);
        sc_s[o] = sc;
        sh_s[o] = fmaf(conv_b[o] - mean[o], sc, beta[o]);
    }

    // ---- phase 1: full w row -> a,d; S; u,v for channel c = tile; meta ----
    {
        const int c = tile;
        const float4* w4 = (const float4*)(w + b * NN);
        float avr[16], dvr[16];
        float s = 0.f;
        #pragma unroll
        for (int k = 0; k < 4; k++) {
            float4 wv = w4[tid + k * 256];
            avr[k*4+0] = relutanh(wv.x);
            avr[k*4+1] = relutanh(wv.y);
            avr[k*4+2] = relutanh(wv.z);
            avr[k*4+3] = relutanh(wv.w);
            s += avr[k*4+0] + avr[k*4+1] + avr[k*4+2] + avr[k*4+3];
        }
        #pragma unroll
        for (int off = 16; off; off >>= 1) s += __shfl_down_sync(0xffffffffu, s, off);
        if ((tid & 31) == 0) red[tid >> 5] = s;
        __syncthreads();
        if (tid == 0) {
            float t = 0.f;
            #pragma unroll
            for (int i = 0; i < 8; i++) t += red[i];
            *(float*)(smem + SM_SSUM) = t;
        }
        __syncthreads();
        const float S = *(float*)(smem + SM_SSUM);
        #pragma unroll
        for (int i = 0; i < 16; i++) dvr[i] = rsqrtf(fmaf(avr[i], S, 1.f));

        if (tid < 64) {
            float aa = relutanh(w[b * NN + n0 + tid]);
            float dd = rsqrtf(fmaf(aa, S, 1.f));
            meta[tid] = make_float4(aa, aa * dd, dd * dd, 0.f);
        }

        const float4* x4 = (const float4*)(x + (size_t)(b * CC + c) * NN);
        float su = 0.f, sv = 0.f;
        #pragma unroll
        for (int k = 0; k < 4; k++) {
            float4 xv = x4[tid + k * 256];
            float t0 = xv.x * avr[k*4+0], t1 = xv.y * avr[k*4+1];
            float t2 = xv.z * avr[k*4+2], t3 = xv.w * avr[k*4+3];
            su += t0 + t1 + t2 + t3;
            sv += t0 * dvr[k*4+0] + t1 * dvr[k*4+1] + t2 * dvr[k*4+2] + t3 * dvr[k*4+3];
        }
        #pragma unroll
        for (int off = 16; off; off >>= 1) {
            su += __shfl_down_sync(0xffffffffu, su, off);
            sv += __shfl_down_sync(0xffffffffu, sv, off);
        }
        if ((tid & 31) == 0) { red[tid >> 5] = su; red2[tid >> 5] = sv; }
        __syncthreads();
        if (tid == 0) {
            float tu = 0.f, tv = 0.f;
            #pragma unroll
            for (int i = 0; i < 8; i++) { tu += red[i]; tv += red2[i]; }
            g_u[b * CC + c] = tu;
            g_v[b * CC + c] = tv;
        }
    }
    __syncthreads();        // A, B, meta complete

    // ---- warp MMA (pre-barrier, registers) ----
    const int m_base = wid * 16;
    const int lrow = lid & 15, lhalf = lid >> 4;
    float dacc[8][4];
    #pragma unroll
    for (int j = 0; j < 8; j++)
        #pragma unroll
        for (int i = 0; i < 4; i++) dacc[j][i] = 0.f;

    #pragma unroll
    for (int kc = 0; kc < 4; kc++) {
        const uint32_t arow = (uint32_t)((m_base + lrow) * 128 + kc * 32 + lhalf * 16);
        uint32_t ahi[4], alo[4];
        ldsm4(ahi, smb + SM_AHI + SWZ(arow));
        ldsm4(alo, smb + SM_ALO + SWZ(arow));
        #pragma unroll
        for (int g = 0; g < 4; g++) {
            const uint32_t brow = (uint32_t)((g * 16 + lrow) * 128 + kc * 32 + lhalf * 16);
            uint32_t bh[4], bl[4];
            ldsm4(bh, smb + SM_BHI + SWZ(brow));
            ldsm4(bl, smb + SM_BLO + SWZ(brow));
            mma_bf16(dacc[2*g],   ahi, bh[0], bh[2]);
            mma_bf16(dacc[2*g+1], ahi, bh[1], bh[3]);
            mma_bf16(dacc[2*g],   ahi, bl[0], bl[2]);
            mma_bf16(dacc[2*g+1], ahi, bl[1], bl[3]);
            mma_bf16(dacc[2*g],   alo, bh[0], bh[2]);
            mma_bf16(dacc[2*g+1], alo, bh[1], bh[3]);
        }
    }

    // ================= device-wide barrier =================
    grid_barrier(tid);

    // ---- u/v -> p/q ----
    if (tid < 64) u_s[tid] = g_u[b * CC + tid];
    else if (tid < 128) v_s[tid - 64] = g_v[b * CC + tid - 64];
    __syncthreads();
    {
        const int o = tid & 63, seg = tid >> 6;
        const float* wr = conv_w + o * 128 + seg * 16;
        const float* uu = u_s + seg * 16;
        const float* vv = v_s + seg * 16;
        float ps = 0.f, qs = 0.f;
        #pragma unroll
        for (int i = 0; i < 16; i += 4) {
            float4 w0 = *(const float4*)(wr + i);
            float4 w1 = *(const float4*)(wr + 64 + i);
            float4 u4 = *(const float4*)(uu + i);
            float4 v4 = *(const float4*)(vv + i);
            ps += w0.x * u4.x + w0.y * u4.y + w0.z * u4.z + w0.w * u4.w;
            qs += w1.x * v4.x + w1.y * v4.y + w1.z * v4.z + w1.w * v4.w;
        }
        ppart[seg * 64 + o] = ps;
        qpart[seg * 64 + o] = qs;
    }
    __syncthreads();
    if (tid < 64)
        p_s[tid] = ppart[tid] + ppart[64 + tid] + ppart[128 + tid] + ppart[192 + tid];
    else if (tid < 128) {
        int o = tid - 64;
        q_s[o] = qpart[o] + qpart[64 + o] + qpart[128 + o] + qpart[192 + o];
    }

    // ---- warps 4-7: bounce D1 (o >= 64) through smem ----
    float* ds1 = (float*)(smem + SM_DS1);
    const int n_e = (lid & 3) * 2;
    const int r_e = lid >> 2;
    if (wid >= 4) {
        const int ol = (wid - 4) * 16 + r_e;
        #pragma unroll
        for (int j = 0; j < 8; j++) {
            *(float2*)(ds1 + ol * 72 + j * 8 + n_e)       = make_float2(dacc[j][0], dacc[j][1]);
            *(float2*)(ds1 + (ol + 8) * 72 + j * 8 + n_e) = make_float2(dacc[j][2], dacc[j][3]);
        }
    }
    __syncthreads();

    // ---- warps 0-3: combine + BN + ReLU + store ----
    if (wid < 4) {
        const int o0 = m_base + r_e;          // 0..63
        const int o1 = o0 + 8;
        const float p0 = p_s[o0], p1 = p_s[o1];
        const float q0 = q_s[o0], q1 = q_s[o1];
        const float c0 = sc_s[o0], c1 = sc_s[o1];
        const float h0 = sh_s[o0], h1 = sh_s[o1];
        float* ob = out + (size_t)(b * CC) * NN + n0;
        #pragma unroll
        for (int j = 0; j < 8; j++) {
            const int n = j * 8 + n_e;
            float4 m0 = meta[n];
            float4 m1 = meta[n + 1];
            float2 e0 = *(const float2*)(ds1 + o0 * 72 + n);
            float2 e1 = *(const float2*)(ds1 + o1 * 72 + n);
            float y00 = fmaf(m0.z, e0.x, dacc[j][0]);
            y00 = fmaf(p0, m0.x, y00); y00 = fmaf(q0, m0.y, y00);
            float y01 = fmaf(m1.z, e0.y, dacc[j][1]);
            y01 = fmaf(p0, m1.x, y01); y01 = fmaf(q0, m1.y, y01);
            float y10 = fmaf(m0.z, e1.x, dacc[j][2]);
            y10 = fmaf(p1, m0.x, y10); y10 = fmaf(q1, m0.y, y10);
            float y11 = fmaf(m1.z, e1.y, dacc[j][3]);
            y11 = fmaf(p1, m1.x, y11); y11 = fmaf(q1, m1.y, y11);
            y00 = fmaxf(fmaf(y00, c0, h0), 0.f);
            y01 = fmaxf(fmaf(y01, c0, h0), 0.f);
            y10 = fmaxf(fmaf(y10, c1, h1), 0.f);
            y11 = fmaxf(fmaf(y11, c1, h1), 0.f);
            *(float2*)(ob + (size_t)o0 * NN + n) = make_float2(y00, y01);
            *(float2*)(ob + (size_t)o1 * NN + n) = make_float2(y10, y11);
        }
    }
}

// -----------------------------------------------------------------------------
extern "C" void kernel_launch(void* const* d_in, const int* in_sizes, int n_in,
                              void* d_out, int out_size) {
    const float* x      = (const float*)d_in[0];
    const float* w      = (const float*)d_in[1];
    const float* conv_w = (const float*)d_in[2];
    const float* conv_b = (const float*)d_in[3];
    const float* gamma  = (const float*)d_in[4];
    const float* beta   = (const float*)d_in[5];
    const float* mean   = (const float*)d_in[6];
    const float* var    = (const float*)d_in[7];
    float* out = (float*)d_out;

    cudaFuncSetAttribute(k_fused, cudaFuncAttributeMaxDynamicSharedMemorySize, SM_TOTAL);
    k_fused<<<GRID, 256, SM_TOTAL>>>(x, w, conv_w, conv_b, gamma, beta, mean, var, out);
}

// round 15
// speedup vs baseline: 1.2816x; 1.1130x over previous
#include <cuda_runtime.h>
#include <cuda_bf16.h>
#include <cstdint>

#define BB 4
#define CC 64
#define NT 64
#define NN 4096
#define GRID 256

typedef unsigned long long ull;

// ---- scratch ----------------------------------------------------------------
__device__ float g_u[BB * CC];
__device__ float g_v[BB * CC];
__device__ unsigned g_bar;

// ---- dynamic smem map (bytes) ----------------------------------------------
#define SM_A     0        // [128 m][64 k] bf16 SW128  16384  (plain bf16)
#define SM_BHI   16384    // [64 n][64 k] bf16 SW128    8192
#define SM_BLO   24576
#define SM_META  32768    // float4[64] {a, a*d, d*d}
#define SM_PS    33792
#define SM_QS    34048
#define SM_SC    34304
#define SM_SH    34560
#define SM_US    34816
#define SM_VS    35072
#define SM_PPART 35328    // 256 f
#define SM_QPART 36352    // 256 f
#define SM_RED   37376
#define SM_RED2  37408
#define SM_SSUM  37440
#define SM_TOTAL 37504
#define SM_DS1   0        // post-barrier overlay (A/B dead): 64 o x 72 stride

#define SWZ(o) ((o) ^ (((o) >> 3) & 0x70))

static __device__ __forceinline__ uint32_t smem_u32(const void* p) {
    uint32_t a;
    asm("{ .reg .u64 t; cvta.to.shared.u64 t, %1; cvt.u32.u64 %0, t; }" : "=r"(a) : "l"(p));
    return a;
}
static __device__ __forceinline__ void ldsm4(uint32_t* r, uint32_t addr) {
    asm volatile("ldmatrix.sync.aligned.m8n8.x4.shared.b16 {%0,%1,%2,%3}, [%4];"
        : "=r"(r[0]), "=r"(r[1]), "=r"(r[2]), "=r"(r[3]) : "r"(addr));
}
static __device__ __forceinline__ void mma_bf16(float* d, const uint32_t* a,
                                                uint32_t b0, uint32_t b1) {
    asm volatile("mma.sync.aligned.m16n8k16.row.col.f32.bf16.bf16.f32 "
        "{%0,%1,%2,%3}, {%4,%5,%6,%7}, {%8,%9}, {%0,%1,%2,%3};"
        : "+f"(d[0]), "+f"(d[1]), "+f"(d[2]), "+f"(d[3])
        : "r"(a[0]), "r"(a[1]), "r"(a[2]), "r"(a[3]), "r"(b0), "r"(b1));
}

static __device__ __forceinline__ float relutanh(float x) {
    if (x <= 0.f) return 0.f;
    float e = __expf(-2.f * x);
    return __fdividef(1.f - e, 1.f + e);
}

static __device__ __forceinline__ void grid_barrier(int tid) {
    __threadfence();
    __syncthreads();
    if (tid == 0) {
        unsigned old = atomicAdd(&g_bar, 1u);
        unsigned target = (old & ~(unsigned)(GRID - 1)) + GRID;
        unsigned vcur;
        do { vcur = *(volatile unsigned*)&g_bar; } while ((int)(vcur - target) < 0);
        __threadfence();
    }
    __syncthreads();
}

static __device__ __forceinline__ void split_store(char* bhi, char* blo,
                                                   uint32_t off, float val) {
    __nv_bfloat16 hi = __float2bfloat16(val);
    __nv_bfloat16 lo = __float2bfloat16(val - __bfloat162float(hi));
    uint32_t sw = SWZ(off);
    *(__nv_bfloat16*)(bhi + sw) = hi;
    *(__nv_bfloat16*)(blo + sw) = lo;
}

// -----------------------------------------------------------------------------
// grid=256, 256 threads. blk -> (b = blk>>6, tile = blk&63), n0 = tile*64.
// Pre-barrier : stage A=[W0;W1] plain bf16 (packed STS.64) + B=x^T hi/lo
//               (SW128); BN fold; phase 1 (a,S,d,u,v for c=tile; tile meta);
//               warp MMA (64 HMMA/warp, 2-term bf16: Ahi*Bhi + Ahi*Blo).
// Post-barrier: u/v -> p/q; warps 4-7 bounce D1 via smem; warps 0-3 combine
//               y = D0 + d^2 D1 + p a + q (a d), BN, ReLU, store.
// -----------------------------------------------------------------------------
__global__ void __launch_bounds__(256, 2) k_fused(
        const float* __restrict__ x,
        const float* __restrict__ w,
        const float* __restrict__ conv_w,
        const float* __restrict__ conv_b,
        const float* __restrict__ gamma,
        const float* __restrict__ beta,
        const float* __restrict__ mean,
        const float* __restrict__ var,
        float* __restrict__ out) {
    extern __shared__ char smem[];
    const uint32_t smb = smem_u32(smem);

    float4* meta = (float4*)(smem + SM_META);
    float* p_s   = (float*)(smem + SM_PS);
    float* q_s   = (float*)(smem + SM_QS);
    float* sc_s  = (float*)(smem + SM_SC);
    float* sh_s  = (float*)(smem + SM_SH);
    float* u_s   = (float*)(smem + SM_US);
    float* v_s   = (float*)(smem + SM_VS);
    float* ppart = (float*)(smem + SM_PPART);
    float* qpart = (float*)(smem + SM_QPART);
    float* red   = (float*)(smem + SM_RED);
    float* red2  = (float*)(smem + SM_RED2);

    const int tid = threadIdx.x;
    const int wid = tid >> 5, lid = tid & 31;
    const int blk = blockIdx.x;
    const int b = blk >> 6;
    const int tile = blk & 63;
    const int n0 = tile * NT;

    // ---- stage A = [W0;W1] plain bf16, SW128, packed 8-byte stores ----
    {
        #pragma unroll
        for (int k = 0; k < 8; k++) {
            int i4 = tid + k * 256;              // 2048 float4
            int m = i4 >> 4, cb = (i4 & 15) * 4;
            const float* src = (m < CC) ? (conv_w + m * 128 + cb)
                                        : (conv_w + (m - CC) * 128 + CC + cb);
            float4 wv = *(const float4*)src;
            __nv_bfloat162 lo2 = __float22bfloat162_rn(make_float2(wv.x, wv.y));
            __nv_bfloat162 hi2 = __float22bfloat162_rn(make_float2(wv.z, wv.w));
            uint32_t lo_u, hi_u;
            memcpy(&lo_u, &lo2, 4);
            memcpy(&hi_u, &hi2, 4);
            ull packed = (ull)lo_u | ((ull)hi_u << 32);
            uint32_t off = (uint32_t)(m * 128 + cb * 2);   // 8-aligned
            *(ull*)(smem + SM_A + SWZ(off)) = packed;
        }
    }
    // ---- stage B[n][c] = x[c][n0+n] hi/lo, SW128 ----
    {
        const int c = tid >> 2;                 // 0..63
        const int nc = (tid & 3) * 16;
        const float* xr = x + (size_t)(b * CC + c) * NN + n0 + nc;
        #pragma unroll
        for (int q4 = 0; q4 < 4; q4++) {
            float4 xv = *(const float4*)(xr + q4 * 4);
            int n = nc + q4 * 4;
            split_store(smem + SM_BHI, smem + SM_BLO, (uint32_t)((n + 0) * 128 + c * 2), xv.x);
            split_store(smem + SM_BHI, smem + SM_BLO, (uint32_t)((n + 1) * 128 + c * 2), xv.y);
            split_store(smem + SM_BHI, smem + SM_BLO, (uint32_t)((n + 2) * 128 + c * 2), xv.z);
            split_store(smem + SM_BHI, smem + SM_BLO, (uint32_t)((n + 3) * 128 + c * 2), xv.w);
        }
    }
    // ---- BN fold ----
    if (tid >= 128 && tid < 192) {
        int o = tid - 128;
        float sc = gamma[o] * rsqrtf(var[o] + 1e-5f);
        sc_s[o] = sc;
        sh_s[o] = fmaf(conv_b[o] - mean[o], sc, beta[o]);
    }

    // ---- phase 1: full w row -> a,d; S; u,v for channel c = tile; meta ----
    {
        const int c = tile;
        const float4* w4 = (const float4*)(w + b * NN);
        float avr[16], dvr[16];
        float s = 0.f;
        #pragma unroll
        for (int k = 0; k < 4; k++) {
            float4 wv = w4[tid + k * 256];
            avr[k*4+0] = relutanh(wv.x);
            avr[k*4+1] = relutanh(wv.y);
            avr[k*4+2] = relutanh(wv.z);
            avr[k*4+3] = relutanh(wv.w);
            s += avr[k*4+0] + avr[k*4+1] + avr[k*4+2] + avr[k*4+3];
        }
        #pragma unroll
        for (int off = 16; off; off >>= 1) s += __shfl_down_sync(0xffffffffu, s, off);
        if ((tid & 31) == 0) red[tid >> 5] = s;
        __syncthreads();
        if (tid == 0) {
            float t = 0.f;
            #pragma unroll
            for (int i = 0; i < 8; i++) t += red[i];
            *(float*)(smem + SM_SSUM) = t;
        }
        __syncthreads();
        const float S = *(float*)(smem + SM_SSUM);
        #pragma unroll
        for (int i = 0; i < 16; i++) dvr[i] = rsqrtf(fmaf(avr[i], S, 1.f));

        if (tid < 64) {
            float aa = relutanh(w[b * NN + n0 + tid]);
            float dd = rsqrtf(fmaf(aa, S, 1.f));
            meta[tid] = make_float4(aa, aa * dd, dd * dd, 0.f);
        }

        const float4* x4 = (const float4*)(x + (size_t)(b * CC + c) * NN);
        float su = 0.f, sv = 0.f;
        #pragma unroll
        for (int k = 0; k < 4; k++) {
            float4 xv = x4[tid + k * 256];
            float t0 = xv.x * avr[k*4+0], t1 = xv.y * avr[k*4+1];
            float t2 = xv.z * avr[k*4+2], t3 = xv.w * avr[k*4+3];
            su += t0 + t1 + t2 + t3;
            sv += t0 * dvr[k*4+0] + t1 * dvr[k*4+1] + t2 * dvr[k*4+2] + t3 * dvr[k*4+3];
        }
        #pragma unroll
        for (int off = 16; off; off >>= 1) {
            su += __shfl_down_sync(0xffffffffu, su, off);
            sv += __shfl_down_sync(0xffffffffu, sv, off);
        }
        if ((tid & 31) == 0) { red[tid >> 5] = su; red2[tid >> 5] = sv; }
        __syncthreads();
        if (tid == 0) {
            float tu = 0.f, tv = 0.f;
            #pragma unroll
            for (int i = 0; i < 8; i++) { tu += red[i]; tv += red2[i]; }
            g_u[b * CC + c] = tu;
            g_v[b * CC + c] = tv;
        }
    }
    __syncthreads();        // A, B, meta complete

    // ---- warp MMA (pre-barrier, registers): D = A*(Bhi+Blo) ----
    const int m_base = wid * 16;
    const int lrow = lid & 15, lhalf = lid >> 4;
    float dacc[8][4];
    #pragma unroll
    for (int j = 0; j < 8; j++)
        #pragma unroll
        for (int i = 0; i < 4; i++) dacc[j][i] = 0.f;

    #pragma unroll
    for (int kc = 0; kc < 4; kc++) {
        const uint32_t arow = (uint32_t)((m_base + lrow) * 128 + kc * 32 + lhalf * 16);
        uint32_t af[4];
        ldsm4(af, smb + SM_A + SWZ(arow));
        #pragma unroll
        for (int g = 0; g < 4; g++) {
            const uint32_t brow = (uint32_t)((g * 16 + lrow) * 128 + kc * 32 + lhalf * 16);
            uint32_t bh[4], bl[4];
            ldsm4(bh, smb + SM_BHI + SWZ(brow));
            ldsm4(bl, smb + SM_BLO + SWZ(brow));
            mma_bf16(dacc[2*g],   af, bh[0], bh[2]);
            mma_bf16(dacc[2*g+1], af, bh[1], bh[3]);
            mma_bf16(dacc[2*g],   af, bl[0], bl[2]);
            mma_bf16(dacc[2*g+1], af, bl[1], bl[3]);
        }
    }

    // ================= device-wide barrier =================
    grid_barrier(tid);

    // ---- u/v -> p/q ----
    if (tid < 64) u_s[tid] = g_u[b * CC + tid];
    else if (tid < 128) v_s[tid - 64] = g_v[b * CC + tid - 64];
    __syncthreads();
    {
        const int o = tid & 63, seg = tid >> 6;
        const float* wr = conv_w + o * 128 + seg * 16;
        const float* uu = u_s + seg * 16;
        const float* vv = v_s + seg * 16;
        float ps = 0.f, qs = 0.f;
        #pragma unroll
        for (int i = 0; i < 16; i += 4) {
            float4 w0 = *(const float4*)(wr + i);
            float4 w1 = *(const float4*)(wr + 64 + i);
            float4 u4 = *(const float4*)(uu + i);
            float4 v4 = *(const float4*)(vv + i);
            ps += w0.x * u4.x + w0.y * u4.y + w0.z * u4.z + w0.w * u4.w;
            qs += w1.x * v4.x + w1.y * v4.y + w1.z * v4.z + w1.w * v4.w;
        }
        ppart[seg * 64 + o] = ps;
        qpart[seg * 64 + o] = qs;
    }
    __syncthreads();
    if (tid < 64)
        p_s[tid] = ppart[tid] + ppart[64 + tid] + ppart[128 + tid] + ppart[192 + tid];
    else if (tid < 128) {
        int o = tid - 64;
        q_s[o] = qpart[o] + qpart[64 + o] + qpart[128 + o] + qpart[192 + o];
    }

    // ---- warps 4-7: bounce D1 (o >= 64) through smem ----
    float* ds1 = (float*)(smem + SM_DS1);
    const int n_e = (lid & 3) * 2;
    const int r_e = lid >> 2;
    if (wid >= 4) {
        const int ol = (wid - 4) * 16 + r_e;
        #pragma unroll
        for (int j = 0; j < 8; j++) {
            *(float2*)(ds1 + ol * 72 + j * 8 + n_e)       = make_float2(dacc[j][0], dacc[j][1]);
            *(float2*)(ds1 + (ol + 8) * 72 + j * 8 + n_e) = make_float2(dacc[j][2], dacc[j][3]);
        }
    }
    __syncthreads();

    // ---- warps 0-3: combine + BN + ReLU + store ----
    if (wid < 4) {
        const int o0 = m_base + r_e;          // 0..63
        const int o1 = o0 + 8;
        const float p0 = p_s[o0], p1 = p_s[o1];
        const float q0 = q_s[o0], q1 = q_s[o1];
        const float c0 = sc_s[o0], c1 = sc_s[o1];
        const float h0 = sh_s[o0], h1 = sh_s[o1];
        float* ob = out + (size_t)(b * CC) * NN + n0;
        #pragma unroll
        for (int j = 0; j < 8; j++) {
            const int n = j * 8 + n_e;
            float4 m0 = meta[n];
            float4 m1 = meta[n + 1];
            float2 e0 = *(const float2*)(ds1 + o0 * 72 + n);
            float2 e1 = *(const float2*)(ds1 + o1 * 72 + n);
            float y00 = fmaf(m0.z, e0.x, dacc[j][0]);
            y00 = fmaf(p0, m0.x, y00); y00 = fmaf(q0, m0.y, y00);
            float y01 = fmaf(m1.z, e0.y, dacc[j][1]);
            y01 = fmaf(p0, m1.x, y01); y01 = fmaf(q0, m1.y, y01);
            float y10 = fmaf(m0.z, e1.x, dacc[j][2]);
            y10 = fmaf(p1, m0.x, y10); y10 = fmaf(q1, m0.y, y10);
            float y11 = fmaf(m1.z, e1.y, dacc[j][3]);
            y11 = fmaf(p1, m1.x, y11); y11 = fmaf(q1, m1.y, y11);
            y00 = fmaxf(fmaf(y00, c0, h0), 0.f);
            y01 = fmaxf(fmaf(y01, c0, h0), 0.f);
            y10 = fmaxf(fmaf(y10, c1, h1), 0.f);
            y11 = fmaxf(fmaf(y11, c1, h1), 0.f);
            *(float2*)(ob + (size_t)o0 * NN + n) = make_float2(y00, y01);
            *(float2*)(ob + (size_t)o1 * NN + n) = make_float2(y10, y11);
        }
    }
}

// -----------------------------------------------------------------------------
extern "C" void kernel_launch(void* const* d_in, const int* in_sizes, int n_in,
                              void* d_out, int out_size) {
    const float* x      = (const float*)d_in[0];
    const float* w      = (const float*)d_in[1];
    const float* conv_w = (const float*)d_in[2];
    const float* conv_b = (const float*)d_in[3];
    const float* gamma  = (const float*)d_in[4];
    const float* beta   = (const float*)d_in[5];
    const float* mean   = (const float*)d_in[6];
    const float* var    = (const float*)d_in[7];
    float* out = (float*)d_out;

    cudaFuncSetAttribute(k_fused, cudaFuncAttributeMaxDynamicSharedMemorySize, SM_TOTAL);
    k_fused<<<GRID, 256, SM_TOTAL>>>(x, w, conv_w, conv_b, gamma, beta, mean, var, out);
}

// round 16
// speedup vs baseline: 1.3041x; 1.0175x over previous
#include <cuda_runtime.h>
#include <cuda_bf16.h>
#include <cstdint>

#define BB 4
#define CC 64
#define NT 64
#define NN 4096
#define GRID 256

typedef unsigned long long ull;

// ---- scratch ----------------------------------------------------------------
__device__ float g_u[BB * CC];
__device__ float g_v[BB * CC];
__device__ unsigned g_bar;

// ---- dynamic smem map (bytes) ----------------------------------------------
#define SM_A     0        // [128 m][64 k] bf16 SW128  16384 (plain bf16)
#define SM_BHI   16384    // [64 k][64 n] bf16 SW128    8192 (row-major k x n)
#define SM_BLO   24576
// post-barrier overlays (A/B dead after pre-barrier MMA)
#define SM_DS0   0        // 64 o x 72 stride fp32     18432
#define SM_DS1   18432    //                           18432
#define SM_META  36864    // float4[64] {a, a*d, d*d}
#define SM_PS    37888
#define SM_QS    38144
#define SM_SC    38400
#define SM_SH    38656
#define SM_US    38912
#define SM_VS    39168
#define SM_PPART 39424    // 256 f
#define SM_QPART 40448    // 256 f
#define SM_RED   41472
#define SM_RED2  41504
#define SM_SSUM  41536
#define SM_TOTAL 41600

#define SWZ(o) ((o) ^ (((o) >> 3) & 0x70))

static __device__ __forceinline__ uint32_t smem_u32(const void* p) {
    uint32_t a;
    asm("{ .reg .u64 t; cvta.to.shared.u64 t, %1; cvt.u32.u64 %0, t; }" : "=r"(a) : "l"(p));
    return a;
}
static __device__ __forceinline__ void ldsm4(uint32_t* r, uint32_t addr) {
    asm volatile("ldmatrix.sync.aligned.m8n8.x4.shared.b16 {%0,%1,%2,%3}, [%4];"
        : "=r"(r[0]), "=r"(r[1]), "=r"(r[2]), "=r"(r[3]) : "r"(addr));
}
static __device__ __forceinline__ void ldsm4t(uint32_t* r, uint32_t addr) {
    asm volatile("ldmatrix.sync.aligned.m8n8.x4.trans.shared.b16 {%0,%1,%2,%3}, [%4];"
        : "=r"(r[0]), "=r"(r[1]), "=r"(r[2]), "=r"(r[3]) : "r"(addr));
}
static __device__ __forceinline__ void mma_bf16(float* d, const uint32_t* a,
                                                uint32_t b0, uint32_t b1) {
    asm volatile("mma.sync.aligned.m16n8k16.row.col.f32.bf16.bf16.f32 "
        "{%0,%1,%2,%3}, {%4,%5,%6,%7}, {%8,%9}, {%0,%1,%2,%3};"
        : "+f"(d[0]), "+f"(d[1]), "+f"(d[2]), "+f"(d[3])
        : "r"(a[0]), "r"(a[1]), "r"(a[2]), "r"(a[3]), "r"(b0), "r"(b1));
}

static __device__ __forceinline__ float relutanh(float x) {
    if (x <= 0.f) return 0.f;
    float e = __expf(-2.f * x);
    return __fdividef(1.f - e, 1.f + e);
}

static __device__ __forceinline__ void grid_barrier(int tid) {
    __threadfence();
    __syncthreads();
    if (tid == 0) {
        unsigned old = atomicAdd(&g_bar, 1u);
        unsigned target = (old & ~(unsigned)(GRID - 1)) + GRID;
        unsigned vcur;
        do { vcur = *(volatile unsigned*)&g_bar; } while ((int)(vcur - target) < 0);
        __threadfence();
    }
    __syncthreads();
}

static __device__ __forceinline__ ull pack_bf16x4(float a, float b, float c, float d) {
    __nv_bfloat162 lo2 = __float22bfloat162_rn(make_float2(a, b));
    __nv_bfloat162 hi2 = __float22bfloat162_rn(make_float2(c, d));
    uint32_t lo_u, hi_u;
    memcpy(&lo_u, &lo2, 4);
    memcpy(&hi_u, &hi2, 4);
    return (ull)lo_u | ((ull)hi_u << 32);
}

// -----------------------------------------------------------------------------
// grid=256, 256 threads. blk -> (b = blk>>6, tile = blk&63), n0 = tile*64.
// Pre-barrier : A=[W0;W1] bf16 + B=x [k][n] hi/lo (packed STS.64, SW128);
//               BN fold; phase 1 (w row + preloaded x row; a,S,d,u,v; meta);
//               warp MMA (64 HMMA: A*Bhi + A*Blo, ldmatrix.trans for B).
// Post-barrier: all warps bounce D through ds0/ds1; u/v -> p/q; all 8 warps
//               combine y = D0 + d^2 D1 + p a + q (a d), BN, ReLU, store.
// -----------------------------------------------------------------------------
__global__ void __launch_bounds__(256, 2) k_fused(
        const float* __restrict__ x,
        const float* __restrict__ w,
        const float* __restrict__ conv_w,
        const float* __restrict__ conv_b,
        const float* __restrict__ gamma,
        const float* __restrict__ beta,
        const float* __restrict__ mean,
        const float* __restrict__ var,
        float* __restrict__ out) {
    extern __shared__ char smem[];
    const uint32_t smb = smem_u32(smem);

    float4* meta = (float4*)(smem + SM_META);
    float* p_s   = (float*)(smem + SM_PS);
    float* q_s   = (float*)(smem + SM_QS);
    float* sc_s  = (float*)(smem + SM_SC);
    float* sh_s  = (float*)(smem + SM_SH);
    float* u_s   = (float*)(smem + SM_US);
    float* v_s   = (float*)(smem + SM_VS);
    float* ppart = (float*)(smem + SM_PPART);
    float* qpart = (float*)(smem + SM_QPART);
    float* red   = (float*)(smem + SM_RED);
    float* red2  = (float*)(smem + SM_RED2);

    const int tid = threadIdx.x;
    const int wid = tid >> 5, lid = tid & 31;
    const int blk = blockIdx.x;
    const int b = blk >> 6;
    const int tile = blk & 63;
    const int n0 = tile * NT;

    // ---- stage A = [W0;W1] plain bf16, SW128, packed STS.64 ----
    {
        #pragma unroll
        for (int k = 0; k < 8; k++) {
            int i4 = tid + k * 256;              // 2048 float4
            int m = i4 >> 4, cb = (i4 & 15) * 4;
            const float* src = (m < CC) ? (conv_w + m * 128 + cb)
                                        : (conv_w + (m - CC) * 128 + CC + cb);
            float4 wv = *(const float4*)src;
            uint32_t off = (uint32_t)(m * 128 + cb * 2);   // 8-aligned
            *(ull*)(smem + SM_A + SWZ(off)) = pack_bf16x4(wv.x, wv.y, wv.z, wv.w);
        }
    }
    // ---- stage B[k=c][n] = x[c][n0+n] hi/lo, SW128, packed STS.64 ----
    {
        const int c = tid >> 2;                 // 0..63
        const int nc = (tid & 3) * 16;
        const float* xr = x + (size_t)(b * CC + c) * NN + n0 + nc;
        #pragma unroll
        for (int q4 = 0; q4 < 4; q4++) {
            float4 xv = *(const float4*)(xr + q4 * 4);
            __nv_bfloat16 h0 = __float2bfloat16(xv.x);
            __nv_bfloat16 h1 = __float2bfloat16(xv.y);
            __nv_bfloat16 h2 = __float2bfloat16(xv.z);
            __nv_bfloat16 h3 = __float2bfloat16(xv.w);
            float l0 = xv.x - __bfloat162float(h0);
            float l1 = xv.y - __bfloat162float(h1);
            float l2 = xv.z - __bfloat162float(h2);
            float l3 = xv.w - __bfloat162float(h3);
            uint32_t hlo, hhi;
            {
                __nv_bfloat162 t0 = __nv_bfloat162(h0, h1);
                __nv_bfloat162 t1 = __nv_bfloat162(h2, h3);
                memcpy(&hlo, &t0, 4);
                memcpy(&hhi, &t1, 4);
            }
            ull hp = (ull)hlo | ((ull)hhi << 32);
            ull lp = pack_bf16x4(l0, l1, l2, l3);
            uint32_t off = (uint32_t)(c * 128 + (nc + q4 * 4) * 2);  // 8-aligned
            *(ull*)(smem + SM_BHI + SWZ(off)) = hp;
            *(ull*)(smem + SM_BLO + SWZ(off)) = lp;
        }
    }
    // ---- BN fold ----
    if (tid >= 128 && tid < 192) {
        int o = tid - 128;
        float sc = gamma[o] * rsqrtf(var[o] + 1e-5f);
        sc_s[o] = sc;
        sh_s[o] = fmaf(conv_b[o] - mean[o], sc, beta[o]);
    }

    // ---- phase 1: w row + PRELOADED x row; a,S,d; u,v for c=tile; meta ----
    {
        const int c = tile;
        const float4* w4  = (const float4*)(w + b * NN);
        const float4* x4u = (const float4*)(x + (size_t)(b * CC + c) * NN);
        float4 wv[4], xu[4];
        #pragma unroll
        for (int k = 0; k < 4; k++) wv[k] = w4[tid + k * 256];
        #pragma unroll
        for (int k = 0; k < 4; k++) xu[k] = x4u[tid + k * 256];   // drains under reduction

        float avr[16];
        float s = 0.f;
        #pragma unroll
        for (int k = 0; k < 4; k++) {
            avr[k*4+0] = relutanh(wv[k].x);
            avr[k*4+1] = relutanh(wv[k].y);
            avr[k*4+2] = relutanh(wv[k].z);
            avr[k*4+3] = relutanh(wv[k].w);
            s += avr[k*4+0] + avr[k*4+1] + avr[k*4+2] + avr[k*4+3];
        }
        #pragma unroll
        for (int off = 16; off; off >>= 1) s += __shfl_down_sync(0xffffffffu, s, off);
        if ((tid & 31) == 0) red[tid >> 5] = s;
        __syncthreads();
        if (tid == 0) {
            float t = 0.f;
            #pragma unroll
            for (int i = 0; i < 8; i++) t += red[i];
            *(float*)(smem + SM_SSUM) = t;
        }
        __syncthreads();
        const float S = *(float*)(smem + SM_SSUM);

        if (tid < 64) {
            float aa = relutanh(w[b * NN + n0 + tid]);
            float dd = rsqrtf(fmaf(aa, S, 1.f));
            meta[tid] = make_float4(aa, aa * dd, dd * dd, 0.f);
        }

        float su = 0.f, sv = 0.f;
        #pragma unroll
        for (int k = 0; k < 4; k++) {
            float d0 = rsqrtf(fmaf(avr[k*4+0], S, 1.f));
            float d1 = rsqrtf(fmaf(avr[k*4+1], S, 1.f));
            float d2 = rsqrtf(fmaf(avr[k*4+2], S, 1.f));
            float d3 = rsqrtf(fmaf(avr[k*4+3], S, 1.f));
            float t0 = xu[k].x * avr[k*4+0], t1 = xu[k].y * avr[k*4+1];
            float t2 = xu[k].z * avr[k*4+2], t3 = xu[k].w * avr[k*4+3];
            su += t0 + t1 + t2 + t3;
            sv += t0 * d0 + t1 * d1 + t2 * d2 + t3 * d3;
        }
        #pragma unroll
        for (int off = 16; off; off >>= 1) {
            su += __shfl_down_sync(0xffffffffu, su, off);
            sv += __shfl_down_sync(0xffffffffu, sv, off);
        }
        if ((tid & 31) == 0) { red[tid >> 5] = su; red2[tid >> 5] = sv; }
        __syncthreads();
        if (tid == 0) {
            float tu = 0.f, tv = 0.f;
            #pragma unroll
            for (int i = 0; i < 8; i++) { tu += red[i]; tv += red2[i]; }
            g_u[b * CC + c] = tu;
            g_v[b * CC + c] = tv;
        }
    }
    __syncthreads();        // A, B, meta complete

    // ---- warp MMA: D = A*(Bhi + Blo), B via ldmatrix.trans ----
    const int m_base = wid * 16;
    const int lrow = lid & 15, lhalf = lid >> 4;
    float dacc[8][4];
    #pragma unroll
    for (int j = 0; j < 8; j++)
        #pragma unroll
        for (int i = 0; i < 4; i++) dacc[j][i] = 0.f;

    #pragma unroll
    for (int kc = 0; kc < 4; kc++) {
        const uint32_t arow = (uint32_t)((m_base + lrow) * 128 + kc * 32 + lhalf * 16);
        uint32_t af[4];
        ldsm4(af, smb + SM_A + SWZ(arow));
        #pragma unroll
        for (int g = 0; g < 4; g++) {
            // B[k][n]: rows = k (kc*16 + lrow), cols = n (g*16 + lhalf*8)
            const uint32_t brow = (uint32_t)((kc * 16 + lrow) * 128 + (g * 16 + lhalf * 8) * 2);
            uint32_t bh[4], bl[4];
            ldsm4t(bh, smb + SM_BHI + SWZ(brow));
            ldsm4t(bl, smb + SM_BLO + SWZ(brow));
            mma_bf16(dacc[2*g],   af, bh[0], bh[1]);   // n 0-7: k0-7, k8-15
            mma_bf16(dacc[2*g+1], af, bh[2], bh[3]);   // n 8-15
            mma_bf16(dacc[2*g],   af, bl[0], bl[1]);
            mma_bf16(dacc[2*g+1], af, bl[2], bl[3]);
        }
    }

    // ================= device-wide barrier =================
    grid_barrier(tid);

    // ---- bounce ALL D through smem (warps 0-3 -> ds0, 4-7 -> ds1) ----
    float* ds0 = (float*)(smem + SM_DS0);
    float* ds1 = (float*)(smem + SM_DS1);
    const int n_e = (lid & 3) * 2;
    const int r_e = lid >> 2;
    {
        float* dsw = (wid < 4) ? ds0 : ds1;
        const int ol = (wid & 3) * 16 + r_e;
        #pragma unroll
        for (int j = 0; j < 8; j++) {
            *(float2*)(dsw + ol * 72 + j * 8 + n_e)       = make_float2(dacc[j][0], dacc[j][1]);
            *(float2*)(dsw + (ol + 8) * 72 + j * 8 + n_e) = make_float2(dacc[j][2], dacc[j][3]);
        }
    }

    // ---- u/v -> p/q ----
    if (tid < 64) u_s[tid] = g_u[b * CC + tid];
    else if (tid < 128) v_s[tid - 64] = g_v[b * CC + tid - 64];
    __syncthreads();
    {
        const int o = tid & 63, seg = tid >> 6;
        const float* wr = conv_w + o * 128 + seg * 16;
        const float* uu = u_s + seg * 16;
        const float* vv = v_s + seg * 16;
        float ps = 0.f, qs = 0.f;
        #pragma unroll
        for (int i = 0; i < 16; i += 4) {
            float4 w0 = *(const float4*)(wr + i);
            float4 w1 = *(const float4*)(wr + 64 + i);
            float4 u4 = *(const float4*)(uu + i);
            float4 v4 = *(const float4*)(vv + i);
            ps += w0.x * u4.x + w0.y * u4.y + w0.z * u4.z + w0.w * u4.w;
            qs += w1.x * v4.x + w1.y * v4.y + w1.z * v4.z + w1.w * v4.w;
        }
        ppart[seg * 64 + o] = ps;
        qpart[seg * 64 + o] = qs;
    }
    __syncthreads();
    if (tid < 64)
        p_s[tid] = ppart[tid] + ppart[64 + tid] + ppart[128 + tid] + ppart[192 + tid];
    else if (tid < 128) {
        int o = tid - 64;
        q_s[o] = qpart[o] + qpart[64 + o] + qpart[128 + o] + qpart[192 + o];
    }
    __syncthreads();

    // ---- combine (ALL 8 warps): warp = (o-slice 16, n-half 32) ----
    {
        const int nh = wid >> 2;
        const int obase = (wid & 3) * 16;
        const int o0 = obase + r_e, o1 = o0 + 8;
        const float p0 = p_s[o0], p1 = p_s[o1];
        const float q0 = q_s[o0], q1 = q_s[o1];
        const float c0 = sc_s[o0], c1 = sc_s[o1];
        const float h0 = sh_s[o0], h1 = sh_s[o1];
        float* ob = out + (size_t)(b * CC) * NN + n0;
        #pragma unroll
        for (int j = 0; j < 4; j++) {
            const int n = nh * 32 + j * 8 + n_e;
            float4 m0 = meta[n];
            float4 m1 = meta[n + 1];
            float2 a0 = *(const float2*)(ds0 + o0 * 72 + n);
            float2 a1 = *(const float2*)(ds0 + o1 * 72 + n);
            float2 e0 = *(const float2*)(ds1 + o0 * 72 + n);
            float2 e1 = *(const float2*)(ds1 + o1 * 72 + n);
            float y00 = fmaf(m0.z, e0.x, a0.x);
            y00 = fmaf(p0, m0.x, y00); y00 = fmaf(q0, m0.y, y00);
            float y01 = fmaf(m1.z, e0.y, a0.y);
            y01 = fmaf(p0, m1.x, y01); y01 = fmaf(q0, m1.y, y01);
            float y10 = fmaf(m0.z, e1.x, a1.x);
            y10 = fmaf(p1, m0.x, y10); y10 = fmaf(q1, m0.y, y10);
            float y11 = fmaf(m1.z, e1.y, a1.y);
            y11 = fmaf(p1, m1.x, y11); y11 = fmaf(q1, m1.y, y11);
            y00 = fmaxf(fmaf(y00, c0, h0), 0.f);
            y01 = fmaxf(fmaf(y01, c0, h0), 0.f);
            y10 = fmaxf(fmaf(y10, c1, h1), 0.f);
            y11 = fmaxf(fmaf(y11, c1, h1), 0.f);
            *(float2*)(ob + (size_t)o0 * NN + n) = make_float2(y00, y01);
            *(float2*)(ob + (size_t)o1 * NN + n) = make_float2(y10, y11);
        }
    }
}

// -----------------------------------------------------------------------------
extern "C" void kernel_launch(void* const* d_in, const int* in_sizes, int n_in,
                              void* d_out, int out_size) {
    const float* x      = (const float*)d_in[0];
    const float* w      = (const float*)d_in[1];
    const float* conv_w = (const float*)d_in[2];
    const float* conv_b = (const float*)d_in[3];
    const float* gamma  = (const float*)d_in[4];
    const float* beta   = (const float*)d_in[5];
    const float* mean   = (const float*)d_in[6];
    const float* var    = (const float*)d_in[7];
    float* out = (float*)d_out;

    cudaFuncSetAttribute(k_fused, cudaFuncAttributeMaxDynamicSharedMemorySize, SM_TOTAL);
    k_fused<<<GRID, 256, SM_TOTAL>>>(x, w, conv_w, conv_b, gamma, beta, mean, var, out);
}